// round 13
// baseline (speedup 1.0000x reference)
#include <cuda_runtime.h>
#include <cuda_fp16.h>
#include <cstddef>

typedef unsigned int u32;

#define B_   16
#define C_   64
#define HW_  96

// ---------------- scratch ----------------------------------------------------
__device__ float g_kf[(size_t)B_ * C_ * HW_ * HW_];
__device__ float g_qf[(size_t)B_ * C_ * HW_ * HW_];
__device__ float g_sc[(size_t)B_ * C_ * 576];
__device__ float g_scp[(size_t)4 * B_ * 9 * 64 * 64];
// pixel-major fp16 hi/lo: [img][y][x][ci]; img 0-15:x1, 16-31:x2, 32-47:vf
__device__ __half g_Xh[(size_t)48 * HW_ * HW_ * 64];
__device__ __half g_Xl[(size_t)48 * HW_ * HW_ * 64];
// weight rows [row][ci]: 0-575 w1, 576-1151 w2, 1152-1727 w3, 1728+ dyn (576/b)
__device__ __half g_Bh[(size_t)11008 * 64];
__device__ __half g_Bl[(size_t)11008 * 64];

// ---------------- mma helpers ------------------------------------------------
__device__ __forceinline__ u32 s2u(const void* p) {
    u32 a; asm("{ .reg .u64 t; cvta.to.shared.u64 t, %1; cvt.u32.u64 %0, t; }" : "=r"(a) : "l"(p));
    return a;
}
__device__ __forceinline__ void ldsm4(u32& r0, u32& r1, u32& r2, u32& r3, u32 addr) {
    asm volatile("ldmatrix.sync.aligned.m8n8.x4.shared.b16 {%0,%1,%2,%3}, [%4];"
        : "=r"(r0), "=r"(r1), "=r"(r2), "=r"(r3) : "r"(addr));
}
__device__ __forceinline__ void mma16816(float* d, const u32* a, const u32* b) {
    asm volatile("mma.sync.aligned.m16n8k16.row.col.f32.f16.f16.f32 "
        "{%0,%1,%2,%3}, {%4,%5,%6,%7}, {%8,%9}, {%0,%1,%2,%3};"
        : "+f"(d[0]), "+f"(d[1]), "+f"(d[2]), "+f"(d[3])
        : "r"(a[0]), "r"(a[1]), "r"(a[2]), "r"(a[3]), "r"(b[0]), "r"(b[1]));
}

// smem layout (144B row pitch; bank stride 4 -> conflict-free LDSM)
#define AH_OFF 0
#define AL_OFF 25920
#define BH_OFF 51840

// ---------------- mma conv ---------------------------------------------------
// NCO=128 (fused kf+vf, per-tap B restage) or NCO=64 (all-tap B staged, syncfree)
// mode 0: fp32 planar out. mode 2 (NCO=128): co<64 -> fp32 kf, co>=64 -> Vh/Vl.
template<int NCO, bool ALLB>
__global__ void __launch_bounds__(256) conv_mma_k(
    const __half* __restrict__ Xh, const __half* __restrict__ Xl,
    const __half* __restrict__ Bh, const __half* __restrict__ Bl,
    int aBase, int brow1, int brow2, int bRowStride, int mode,
    float* __restrict__ outF, __half* __restrict__ Vh, __half* __restrict__ Vl)
{
    constexpr int NF = NCO / 16;        // n-frags of 8 co per warp
    constexpr int NJ = NCO / 32;        // 16-co ldsm tiles per warp
    constexpr int NBROWS = ALLB ? 576 : NCO;
    const int BL_OFF_ = BH_OFF + NBROWS * 144;

    extern __shared__ __align__(16) char sm[];
    const u32 sb = s2u(sm);
    const int t = threadIdx.x, lane = t & 31, wid = t >> 5;
    const int m0 = (wid & 3) * 32, n0 = (wid >> 2) * (NCO / 2);
    const int b = blockIdx.z;
    const int x0 = blockIdx.x * 16, y0 = blockIdx.y * 8;
    const int br1 = brow1 + b * bRowStride;

    // ---- stage halo once: 180 rows (10y x 18x) x 8 segs, hi+lo ----
    {
        const __half* XhB = Xh + (size_t)(aBase + b) * 9216 * 64;
        const __half* XlB = Xl + (size_t)(aBase + b) * 9216 * 64;
        for (int i = t; i < 1440; i += 256) {
            int row = i >> 3, seg = i & 7;
            int hy = row / 18, hx = row - hy * 18;
            int gy = y0 + hy - 1, gx = x0 + hx - 1;
            float4 vh = make_float4(0.f, 0.f, 0.f, 0.f), vl = vh;
            if ((unsigned)gy < 96u && (unsigned)gx < 96u) {
                size_t g = ((size_t)gy * 96 + gx) * 64 + seg * 8;
                vh = *(const float4*)(XhB + g);
                vl = *(const float4*)(XlB + g);
            }
            *(float4*)(sm + AH_OFF + row * 144 + seg * 16) = vh;
            *(float4*)(sm + AL_OFF + row * 144 + seg * 16) = vl;
        }
    }
    if (ALLB) {   // stage all 9 taps of B once (rows: tap*64+co)
        for (int i = t; i < NBROWS * 8; i += 256) {
            int row = i >> 3, seg = i & 7;
            size_t g = (size_t)(br1 + row) * 64 + seg * 8;
            *(float4*)(sm + BH_OFF + row * 144 + seg * 16) = *(const float4*)(Bh + g);
            *(float4*)(sm + BL_OFF_ + row * 144 + seg * 16) = *(const float4*)(Bl + g);
        }
        __syncthreads();
    }

    // lane geometry
    const int aRowL = (lane & 7) + 8 * ((lane >> 3) & 1);
    const int aKb   = 16 * (lane >> 4);
    const int bCoL  = (lane & 7) + 8 * (lane >> 4);
    const int bKb   = 16 * ((lane >> 3) & 1);

    float acc[2][NF][4];
#pragma unroll
    for (int i = 0; i < 2; i++)
#pragma unroll
        for (int j = 0; j < NF; j++)
#pragma unroll
            for (int k = 0; k < 4; k++) acc[i][j][k] = 0.f;

#pragma unroll 1
    for (int tap = 0; tap < 9; tap++) {
        int bRowOff;
        if (!ALLB) {
            __syncthreads();   // prior tap ldsm done before overwrite
            for (int i = t; i < NCO * 8; i += 256) {
                int co = i >> 3, seg = i & 7;
                int src = (NCO == 128 && co >= 64) ? (brow2 + tap * 64 + co - 64)
                                                   : (br1 + tap * 64 + co);
                size_t g = (size_t)src * 64 + seg * 8;
                *(float4*)(sm + BH_OFF + co * 144 + seg * 16) = *(const float4*)(Bh + g);
                *(float4*)(sm + BL_OFF_ + co * 144 + seg * 16) = *(const float4*)(Bl + g);
            }
            __syncthreads();
            bRowOff = 0;
        } else {
            bRowOff = tap * 64;
        }

        const int kh = tap / 3, kw = tap - kh * 3;
        u32 aAddr[2], bAddr[NJ];
#pragma unroll
        for (int f = 0; f < 2; f++) {
            int px = m0 + f * 16 + aRowL;
            int r = ((px >> 4) + kh) * 18 + (px & 15) + kw;
            aAddr[f] = sb + AH_OFF + r * 144 + aKb;
        }
#pragma unroll
        for (int j = 0; j < NJ; j++)
            bAddr[j] = sb + BH_OFF + (bRowOff + n0 + j * 16 + bCoL) * 144 + bKb;

#pragma unroll
        for (int ks = 0; ks < 4; ks++) {
            u32 Ah[2][4], Al[2][4], Bhf[NJ][4], Blf[NJ][4];
#pragma unroll
            for (int f = 0; f < 2; f++) {
                u32 a = aAddr[f] + ks * 32;
                ldsm4(Ah[f][0], Ah[f][1], Ah[f][2], Ah[f][3], a);
                ldsm4(Al[f][0], Al[f][1], Al[f][2], Al[f][3], a + (AL_OFF - AH_OFF));
            }
#pragma unroll
            for (int j = 0; j < NJ; j++) {
                u32 a = bAddr[j] + ks * 32;
                ldsm4(Bhf[j][0], Bhf[j][1], Bhf[j][2], Bhf[j][3], a);
                ldsm4(Blf[j][0], Blf[j][1], Blf[j][2], Blf[j][3], a + (BL_OFF_ - BH_OFF));
            }
            // product-major order: long dependency distance on each acc
#pragma unroll
            for (int mf = 0; mf < 2; mf++)
#pragma unroll
                for (int nf = 0; nf < NF; nf++)
                    mma16816(acc[mf][nf], Ah[mf], &Bhf[nf >> 1][(nf & 1) * 2]);
#pragma unroll
            for (int mf = 0; mf < 2; mf++)
#pragma unroll
                for (int nf = 0; nf < NF; nf++)
                    mma16816(acc[mf][nf], Ah[mf], &Blf[nf >> 1][(nf & 1) * 2]);
#pragma unroll
            for (int mf = 0; mf < 2; mf++)
#pragma unroll
                for (int nf = 0; nf < NF; nf++)
                    mma16816(acc[mf][nf], Al[mf], &Bhf[nf >> 1][(nf & 1) * 2]);
        }
    }

    // ---- epilogue ----
    const int g = lane >> 2, tt = lane & 3;
    const bool toHalf = (mode == 2) && (n0 >= 64);
    if (!toHalf) {
        float* ob = outF + (size_t)b * C_ * 9216;
#pragma unroll
        for (int mf = 0; mf < 2; mf++)
#pragma unroll
            for (int nf = 0; nf < NF; nf++) {
                int co = n0 + nf * 8 + 2 * tt;
#pragma unroll
                for (int h = 0; h < 2; h++) {
                    int px = m0 + mf * 16 + g + h * 8;
                    int y = y0 + (px >> 4), x = x0 + (px & 15);
                    ob[(size_t)co * 9216 + y * 96 + x]       = acc[mf][nf][2 * h];
                    ob[(size_t)(co + 1) * 9216 + y * 96 + x] = acc[mf][nf][2 * h + 1];
                }
            }
    } else {
#pragma unroll
        for (int mf = 0; mf < 2; mf++)
#pragma unroll
            for (int nf = 0; nf < NF; nf++) {
                int col = nf * 8 + 2 * tt;   // local co within vf (warp covers 64)
#pragma unroll
                for (int h = 0; h < 2; h++) {
                    int px = m0 + mf * 16 + g + h * 8;
                    int y = y0 + (px >> 4), x = x0 + (px & 15);
                    size_t ad = ((size_t)(32 + b) * 9216 + (size_t)y * 96 + x) * 64 + col;
                    float v0 = acc[mf][nf][2 * h], v1 = acc[mf][nf][2 * h + 1];
                    __half h0 = __float2half(v0), h1 = __float2half(v1);
                    __half l0 = __float2half(v0 - __half2float(h0));
                    __half l1 = __float2half(v1 - __half2float(h1));
                    *(__half2*)(Vh + ad) = __halves2half2(h0, h1);
                    *(__half2*)(Vl + ad) = __halves2half2(l0, l1);
                }
            }
    }
}

// ---------------- input transpose + fp16 hi/lo split -------------------------
__global__ __launch_bounds__(256) void convert_x_k(
    const float* __restrict__ x1, const float* __restrict__ x2,
    __half* __restrict__ Xh, __half* __restrict__ Xl)
{
    __shared__ float smt[96 * 65];
    const int y = blockIdx.x, b = blockIdx.y, src = blockIdx.z;
    const int t = threadIdx.x;
    const float* xp = (src ? x2 : x1) + (size_t)b * C_ * 9216 + (size_t)y * 96;
    for (int idx = t; idx < 64 * 96; idx += 256) {
        int ci = idx / 96, x = idx - ci * 96;
        smt[x * 65 + ci] = xp[(size_t)ci * 9216 + x];
    }
    __syncthreads();
    size_t base = ((size_t)((src * 16 + b) * 96 + y)) * 96 * 64;
    for (int idx = t; idx < 96 * 64; idx += 256) {
        int x = idx >> 6, ci = idx & 63;
        float v = smt[x * 65 + ci];
        __half h = __float2half(v);
        Xh[base + idx] = h;
        Xl[base + idx] = __float2half(v - __half2float(h));
    }
}

// ---------------- weight gather + fp16 hi/lo split ---------------------------
__global__ __launch_bounds__(64) void convert_w_k(
    const float* __restrict__ w, __half* __restrict__ Bh, __half* __restrict__ Bl,
    int rowBase, int sStride, int rowBS)
{
    const int tap = blockIdx.x >> 6, co = blockIdx.x & 63, b = blockIdx.y, ci = threadIdx.x;
    float v = w[(size_t)b * sStride + co * 576 + ci * 9 + tap];
    size_t row = (size_t)(rowBase + b * rowBS + tap * 64 + co);
    __half h = __float2half(v);
    Bh[row * 64 + ci] = h;
    Bl[row * 64 + ci] = __float2half(v - __half2float(h));
}

// ---------------- scores partials --------------------------------------------
__global__ __launch_bounds__(256) void scores_k(
    const float* __restrict__ kf, const float* __restrict__ qf, float* __restrict__ scp)
{
    __shared__ float ks[C_][33];
    __shared__ float qs[C_][33];
    const int k = blockIdx.x, ch = blockIdx.y, b = blockIdx.z;
    const int kh = k / 3, kw = k - kh * 3;
    const int t = threadIdx.x;
    const int tc = t >> 4, td = t & 15;
    const float* kb = kf + (size_t)b * C_ * 9216;
    const float* qb = qf + (size_t)b * C_ * 9216;
    float acc[4][4] = {};
#pragma unroll 1
    for (int hp = ch * 8; hp < ch * 8 + 8; hp++) {
        __syncthreads();
        const int y = hp * 3 + kh;
        for (int idx = t; idx < C_ * 32; idx += 256) {
            int c = idx >> 5, wp = idx & 31;
            size_t off = ((size_t)c * 96 + y) * 96 + wp * 3 + kw;
            ks[c][wp] = kb[off];
            qs[c][wp] = qb[off];
        }
        __syncthreads();
#pragma unroll 4
        for (int l = 0; l < 32; l++) {
            float kv[4], qv[4];
#pragma unroll
            for (int i = 0; i < 4; i++) { kv[i] = ks[tc * 4 + i][l]; qv[i] = qs[td * 4 + i][l]; }
#pragma unroll
            for (int i = 0; i < 4; i++)
#pragma unroll
                for (int j = 0; j < 4; j++) acc[i][j] += kv[i] * qv[j];
        }
    }
    float* p = scp + ((size_t)((ch * 16 + b) * 9 + k)) * 4096;
#pragma unroll
    for (int i = 0; i < 4; i++)
#pragma unroll
        for (int j = 0; j < 4; j++)
            p[(tc * 4 + i) * 64 + (td * 4 + j)] = acc[i][j];
}

// ---------------- softmax ----------------------------------------------------
__global__ __launch_bounds__(256) void softmax_k(
    const float* __restrict__ scp, float* __restrict__ s)
{
    __shared__ float red[8];
    const int b = blockIdx.x >> 6, d = blockIdx.x & 63;
    const int t = threadIdx.x;
    const float scale = 1.f / 24.f;

    float v[3];
#pragma unroll
    for (int u = 0; u < 3; u++) {
        int e = t + u * 256;
        if (e < 576) {
            int c = e / 9, k = e - c * 9;
            float sum = 0.f;
#pragma unroll
            for (int chn = 0; chn < 4; chn++)
                sum += scp[((size_t)((chn * 16 + b) * 9 + k)) * 4096 + c * 64 + d];
            v[u] = sum * scale;
        } else v[u] = -3.4e38f;
    }

    float m = fmaxf(fmaxf(v[0], v[1]), v[2]);
#pragma unroll
    for (int o = 16; o; o >>= 1) m = fmaxf(m, __shfl_xor_sync(0xffffffffu, m, o));
    if ((t & 31) == 0) red[t >> 5] = m;
    __syncthreads();
    m = fmaxf(fmaxf(fmaxf(red[0], red[1]), fmaxf(red[2], red[3])),
              fmaxf(fmaxf(red[4], red[5]), fmaxf(red[6], red[7])));
    __syncthreads();

    float e0 = __expf(v[0] - m), e1 = __expf(v[1] - m);
    float e2 = (t + 512) < 576 ? __expf(v[2] - m) : 0.f;
    float sum = e0 + e1 + e2;
#pragma unroll
    for (int o = 16; o; o >>= 1) sum += __shfl_xor_sync(0xffffffffu, sum, o);
    if ((t & 31) == 0) red[t >> 5] = sum;
    __syncthreads();
    sum = red[0] + red[1] + red[2] + red[3] + red[4] + red[5] + red[6] + red[7];

    float inv = 1.f / sum;
    float* p = s + (size_t)(b * C_ + d) * 576;
    p[t] = e0 * inv;
    p[t + 256] = e1 * inv;
    if (t + 512 < 576) p[t + 512] = e2 * inv;
}

// ---------------- launch -----------------------------------------------------
extern "C" void kernel_launch(void* const* d_in, const int* in_sizes, int n_in,
                              void* d_out, int out_size)
{
    const float* x1 = (const float*)d_in[0];
    const float* x2 = (const float*)d_in[1];
    const float* w1 = (const float*)d_in[2];
    const float* w2 = (const float*)d_in[3];
    const float* w3 = (const float*)d_in[4];
    float* out = (float*)d_out;

    float *kf, *qf, *sc, *scp;
    __half *Xh, *Xl, *Bh, *Bl;
    cudaGetSymbolAddress((void**)&kf, g_kf);
    cudaGetSymbolAddress((void**)&qf, g_qf);
    cudaGetSymbolAddress((void**)&sc, g_sc);
    cudaGetSymbolAddress((void**)&scp, g_scp);
    cudaGetSymbolAddress((void**)&Xh, g_Xh);
    cudaGetSymbolAddress((void**)&Xl, g_Xl);
    cudaGetSymbolAddress((void**)&Bh, g_Bh);
    cudaGetSymbolAddress((void**)&Bl, g_Bl);

    const int SM_FUSED = 51840 + 2 * 128 * 144;   // 88704
    const int SM_ALLB  = 51840 + 2 * 576 * 144;   // 217728
    cudaFuncSetAttribute((const void*)conv_mma_k<128, false>,
                         cudaFuncAttributeMaxDynamicSharedMemorySize, SM_FUSED);
    cudaFuncSetAttribute((const void*)conv_mma_k<64, true>,
                         cudaFuncAttributeMaxDynamicSharedMemorySize, SM_ALLB);

    convert_x_k<<<dim3(96, 16, 2), 256>>>(x1, x2, Xh, Xl);
    convert_w_k<<<dim3(576, 1), 64>>>(w1, Bh, Bl, 0, 0, 0);
    convert_w_k<<<dim3(576, 1), 64>>>(w2, Bh, Bl, 576, 0, 0);
    convert_w_k<<<dim3(576, 1), 64>>>(w3, Bh, Bl, 1152, 0, 0);

    dim3 g(6, 12, 16);
    // fused kf (co 0-63, fp32) + vf (co 64-127 -> fp16 hi/lo pixel-major)
    conv_mma_k<128, false><<<g, 256, SM_FUSED>>>(Xh, Xl, Bh, Bl, 0, 0, 1152, 0, 2, kf, Xh, Xl);
    // qf: all-tap staged, sync-free mainloop
    conv_mma_k<64, true><<<g, 256, SM_ALLB>>>(Xh, Xl, Bh, Bl, 16, 576, 0, 0, 0, qf, 0, 0);

    scores_k<<<dim3(9, 4, 16), 256>>>(kf, qf, scp);
    softmax_k<<<B_ * C_, 256>>>(scp, sc);
    convert_w_k<<<dim3(576, 16), 64>>>(sc, Bh, Bl, 1728, C_ * 576, 576);

    // dynamic conv on vf: per-batch weights, row stride 576 (FIXED arg order)
    conv_mma_k<64, true><<<g, 256, SM_ALLB>>>(Xh, Xl, Bh, Bl, 32, 1728, 0, 576, 0, out, 0, 0);
}

// round 15
// speedup vs baseline: 1.1536x; 1.1536x over previous
#include <cuda_runtime.h>
#include <cuda_fp16.h>
#include <cstddef>

typedef unsigned int u32;

#define B_   16
#define C_   64
#define HW_  96

// ---------------- scratch ----------------------------------------------------
__device__ float g_kf[(size_t)B_ * C_ * HW_ * HW_];
__device__ float g_qf[(size_t)B_ * C_ * HW_ * HW_];
__device__ float g_sc[(size_t)B_ * C_ * 576];
__device__ float g_scp[(size_t)4 * B_ * 9 * 64 * 64];
// pixel-major fp16 hi/lo: [img][y][x][ci]; img 0-15:x1, 16-31:x2, 32-47:vf
__device__ __half g_Xh[(size_t)48 * HW_ * HW_ * 64];
__device__ __half g_Xl[(size_t)48 * HW_ * HW_ * 64];
// weight rows [row][ci]: 0-575 w1, 576-1151 w2, 1152-1727 w3, 1728+ dyn (576/b)
__device__ __half g_Bh[(size_t)11008 * 64];
__device__ __half g_Bl[(size_t)11008 * 64];

// ---------------- mma helpers ------------------------------------------------
__device__ __forceinline__ u32 s2u(const void* p) {
    u32 a; asm("{ .reg .u64 t; cvta.to.shared.u64 t, %1; cvt.u32.u64 %0, t; }" : "=r"(a) : "l"(p));
    return a;
}
__device__ __forceinline__ void ldsm4(u32& r0, u32& r1, u32& r2, u32& r3, u32 addr) {
    asm volatile("ldmatrix.sync.aligned.m8n8.x4.shared.b16 {%0,%1,%2,%3}, [%4];"
        : "=r"(r0), "=r"(r1), "=r"(r2), "=r"(r3) : "r"(addr));
}
__device__ __forceinline__ void mma16816(float* d, const u32* a, const u32* b) {
    asm volatile("mma.sync.aligned.m16n8k16.row.col.f32.f16.f16.f32 "
        "{%0,%1,%2,%3}, {%4,%5,%6,%7}, {%8,%9}, {%0,%1,%2,%3};"
        : "+f"(d[0]), "+f"(d[1]), "+f"(d[2]), "+f"(d[3])
        : "r"(a[0]), "r"(a[1]), "r"(a[2]), "r"(a[3]), "r"(b[0]), "r"(b[1]));
}

// smem layout (144B row pitch; bank stride 4 -> conflict-free LDSM)
#define AH_OFF 0
#define AL_OFF 25920
#define BB_OFF 51840
// B stage: hi rows then lo rows; NCO=64 double-buffered (2 stages), NCO=128 single.
// Both configs total 88704 bytes -> 2 blocks/SM.

// ---------------- mma conv ---------------------------------------------------
// mode 0: fp32 planar out. mode 2 (NCO=128): co<64 -> fp32 kf, co>=64 -> Vh/Vl.
template<int NCO, bool DB>
__global__ void __launch_bounds__(256) conv_mma_k(
    const __half* __restrict__ Xh, const __half* __restrict__ Xl,
    const __half* __restrict__ Bh, const __half* __restrict__ Bl,
    int aBase, int brow1, int brow2, int bRowStride, int mode,
    float* __restrict__ outF, __half* __restrict__ Vh, __half* __restrict__ Vl)
{
    constexpr int NF = NCO / 16;          // n-frags of 8 co per warp
    constexpr int NJ = NCO / 32;          // 16-co ldsm tiles per warp
    constexpr int BSTG = NCO * 144 * 2;   // one stage: hi + lo
    constexpr int BLO  = NCO * 144;       // lo offset within stage

    extern __shared__ __align__(16) char sm[];
    const u32 sb = s2u(sm);
    const int t = threadIdx.x, lane = t & 31, wid = t >> 5;
    const int m0 = (wid & 3) * 32, n0 = (wid >> 2) * (NCO / 2);
    const int b = blockIdx.z;
    const int x0 = blockIdx.x * 16, y0 = blockIdx.y * 8;
    const int br1 = brow1 + b * bRowStride;

    // ---- stage halo once: 180 rows (10y x 18x) x 8 segs, hi+lo ----
    {
        const __half* XhB = Xh + (size_t)(aBase + b) * 9216 * 64;
        const __half* XlB = Xl + (size_t)(aBase + b) * 9216 * 64;
        for (int i = t; i < 1440; i += 256) {
            int row = i >> 3, seg = i & 7;
            int hy = row / 18, hx = row - hy * 18;
            int gy = y0 + hy - 1, gx = x0 + hx - 1;
            float4 vh = make_float4(0.f, 0.f, 0.f, 0.f), vl = vh;
            if ((unsigned)gy < 96u && (unsigned)gx < 96u) {
                size_t g = ((size_t)gy * 96 + gx) * 64 + seg * 8;
                vh = *(const float4*)(XhB + g);
                vl = *(const float4*)(XlB + g);
            }
            *(float4*)(sm + AH_OFF + row * 144 + seg * 16) = vh;
            *(float4*)(sm + AL_OFF + row * 144 + seg * 16) = vl;
        }
    }

    // B staging helper (one tap into stage sidx)
    auto stageB = [&](int sidx, int tap) {
        char* bb = sm + BB_OFF + sidx * BSTG;
        for (int i = t; i < NCO * 8; i += 256) {
            int co = i >> 3, seg = i & 7;
            int src = (NCO == 128 && co >= 64) ? (brow2 + tap * 64 + co - 64)
                                               : (br1 + tap * 64 + co);
            size_t g = (size_t)src * 64 + seg * 8;
            *(float4*)(bb + co * 144 + seg * 16)       = *(const float4*)(Bh + g);
            *(float4*)(bb + BLO + co * 144 + seg * 16) = *(const float4*)(Bl + g);
        }
    };

    // lane geometry
    const int aRowL = (lane & 7) + 8 * ((lane >> 3) & 1);
    const int aKb   = 16 * (lane >> 4);
    const int bCoL  = (lane & 7) + 8 * (lane >> 4);
    const int bKb   = 16 * ((lane >> 3) & 1);

    float acc[2][NF][4];
#pragma unroll
    for (int i = 0; i < 2; i++)
#pragma unroll
        for (int j = 0; j < NF; j++)
#pragma unroll
            for (int k = 0; k < 4; k++) acc[i][j][k] = 0.f;

    if (DB) { stageB(0, 0); }
    __syncthreads();

#pragma unroll 1
    for (int tap = 0; tap < 9; tap++) {
        int bStage;
        if (DB) {
            bStage = tap & 1;
            if (tap < 8) stageB(bStage ^ 1, tap + 1);   // overlap with compute
        } else {
            if (tap) __syncthreads();   // prior tap ldsm done before overwrite
            stageB(0, tap);
            __syncthreads();
            bStage = 0;
        }

        const int kh = tap / 3, kw = tap - kh * 3;
        const u32 bbase = sb + BB_OFF + bStage * BSTG;
        u32 aAddr[2], bAddr[NJ];
#pragma unroll
        for (int f = 0; f < 2; f++) {
            int px = m0 + f * 16 + aRowL;
            int r = ((px >> 4) + kh) * 18 + (px & 15) + kw;
            aAddr[f] = sb + AH_OFF + r * 144 + aKb;
        }
#pragma unroll
        for (int j = 0; j < NJ; j++)
            bAddr[j] = bbase + (n0 + j * 16 + bCoL) * 144 + bKb;

#pragma unroll
        for (int ks = 0; ks < 4; ks++) {
            u32 Ah[2][4], Al[2][4], Bhf[NJ][4], Blf[NJ][4];
#pragma unroll
            for (int f = 0; f < 2; f++) {
                u32 a = aAddr[f] + ks * 32;
                ldsm4(Ah[f][0], Ah[f][1], Ah[f][2], Ah[f][3], a);
                ldsm4(Al[f][0], Al[f][1], Al[f][2], Al[f][3], a + (AL_OFF - AH_OFF));
            }
#pragma unroll
            for (int j = 0; j < NJ; j++) {
                u32 a = bAddr[j] + ks * 32;
                ldsm4(Bhf[j][0], Bhf[j][1], Bhf[j][2], Bhf[j][3], a);
                ldsm4(Blf[j][0], Blf[j][1], Blf[j][2], Blf[j][3], a + BLO);
            }
            // product-major order: long dependency distance on each acc
#pragma unroll
            for (int mf = 0; mf < 2; mf++)
#pragma unroll
                for (int nf = 0; nf < NF; nf++)
                    mma16816(acc[mf][nf], Ah[mf], &Bhf[nf >> 1][(nf & 1) * 2]);
#pragma unroll
            for (int mf = 0; mf < 2; mf++)
#pragma unroll
                for (int nf = 0; nf < NF; nf++)
                    mma16816(acc[mf][nf], Ah[mf], &Blf[nf >> 1][(nf & 1) * 2]);
#pragma unroll
            for (int mf = 0; mf < 2; mf++)
#pragma unroll
                for (int nf = 0; nf < NF; nf++)
                    mma16816(acc[mf][nf], Al[mf], &Bhf[nf >> 1][(nf & 1) * 2]);
        }
        if (DB) __syncthreads();        // staging of next stage visible; reads done
    }

    // ---- epilogue ----
    const int g = lane >> 2, tt = lane & 3;
    const bool toHalf = (mode == 2) && (n0 >= 64);
    if (!toHalf) {
        float* ob = outF + (size_t)b * C_ * 9216;
#pragma unroll
        for (int mf = 0; mf < 2; mf++)
#pragma unroll
            for (int nf = 0; nf < NF; nf++) {
                int co = n0 + nf * 8 + 2 * tt;
#pragma unroll
                for (int h = 0; h < 2; h++) {
                    int px = m0 + mf * 16 + g + h * 8;
                    int y = y0 + (px >> 4), x = x0 + (px & 15);
                    ob[(size_t)co * 9216 + y * 96 + x]       = acc[mf][nf][2 * h];
                    ob[(size_t)(co + 1) * 9216 + y * 96 + x] = acc[mf][nf][2 * h + 1];
                }
            }
    } else {
#pragma unroll
        for (int mf = 0; mf < 2; mf++)
#pragma unroll
            for (int nf = 0; nf < NF; nf++) {
                int col = nf * 8 + 2 * tt;   // local co within vf (warp covers 64)
#pragma unroll
                for (int h = 0; h < 2; h++) {
                    int px = m0 + mf * 16 + g + h * 8;
                    int y = y0 + (px >> 4), x = x0 + (px & 15);
                    size_t ad = ((size_t)(32 + b) * 9216 + (size_t)y * 96 + x) * 64 + col;
                    float v0 = acc[mf][nf][2 * h], v1 = acc[mf][nf][2 * h + 1];
                    __half h0 = __float2half(v0), h1 = __float2half(v1);
                    __half l0 = __float2half(v0 - __half2float(h0));
                    __half l1 = __float2half(v1 - __half2float(h1));
                    *(__half2*)(Vh + ad) = __halves2half2(h0, h1);
                    *(__half2*)(Vl + ad) = __halves2half2(l0, l1);
                }
            }
    }
}

// ---------------- input transpose + fp16 hi/lo split -------------------------
__global__ __launch_bounds__(256) void convert_x_k(
    const float* __restrict__ x1, const float* __restrict__ x2,
    __half* __restrict__ Xh, __half* __restrict__ Xl)
{
    __shared__ float smt[96 * 65];
    const int y = blockIdx.x, b = blockIdx.y, src = blockIdx.z;
    const int t = threadIdx.x;
    const float* xp = (src ? x2 : x1) + (size_t)b * C_ * 9216 + (size_t)y * 96;
    for (int idx = t; idx < 64 * 96; idx += 256) {
        int ci = idx / 96, x = idx - ci * 96;
        smt[x * 65 + ci] = xp[(size_t)ci * 9216 + x];
    }
    __syncthreads();
    size_t base = ((size_t)((src * 16 + b) * 96 + y)) * 96 * 64;
    for (int idx = t; idx < 96 * 64; idx += 256) {
        int x = idx >> 6, ci = idx & 63;
        float v = smt[x * 65 + ci];
        __half h = __float2half(v);
        Xh[base + idx] = h;
        Xl[base + idx] = __float2half(v - __half2float(h));
    }
}

// ---------------- weight gather + fp16 hi/lo split ---------------------------
__global__ __launch_bounds__(64) void convert_w_k(
    const float* __restrict__ w, __half* __restrict__ Bh, __half* __restrict__ Bl,
    int rowBase, int sStride, int rowBS)
{
    const int tap = blockIdx.x >> 6, co = blockIdx.x & 63, b = blockIdx.y, ci = threadIdx.x;
    float v = w[(size_t)b * sStride + co * 576 + ci * 9 + tap];
    size_t row = (size_t)(rowBase + b * rowBS + tap * 64 + co);
    __half h = __float2half(v);
    Bh[row * 64 + ci] = h;
    Bl[row * 64 + ci] = __float2half(v - __half2float(h));
}

// ---------------- scores partials --------------------------------------------
__global__ __launch_bounds__(256) void scores_k(
    const float* __restrict__ kf, const float* __restrict__ qf, float* __restrict__ scp)
{
    __shared__ float ks[C_][33];
    __shared__ float qs[C_][33];
    const int k = blockIdx.x, ch = blockIdx.y, b = blockIdx.z;
    const int kh = k / 3, kw = k - kh * 3;
    const int t = threadIdx.x;
    const int tc = t >> 4, td = t & 15;
    const float* kb = kf + (size_t)b * C_ * 9216;
    const float* qb = qf + (size_t)b * C_ * 9216;
    float acc[4][4] = {};
#pragma unroll 1
    for (int hp = ch * 8; hp < ch * 8 + 8; hp++) {
        __syncthreads();
        const int y = hp * 3 + kh;
        for (int idx = t; idx < C_ * 32; idx += 256) {
            int c = idx >> 5, wp = idx & 31;
            size_t off = ((size_t)c * 96 + y) * 96 + wp * 3 + kw;
            ks[c][wp] = kb[off];
            qs[c][wp] = qb[off];
        }
        __syncthreads();
#pragma unroll 4
        for (int l = 0; l < 32; l++) {
            float kv[4], qv[4];
#pragma unroll
            for (int i = 0; i < 4; i++) { kv[i] = ks[tc * 4 + i][l]; qv[i] = qs[td * 4 + i][l]; }
#pragma unroll
            for (int i = 0; i < 4; i++)
#pragma unroll
                for (int j = 0; j < 4; j++) acc[i][j] += kv[i] * qv[j];
        }
    }
    float* p = scp + ((size_t)((ch * 16 + b) * 9 + k)) * 4096;
#pragma unroll
    for (int i = 0; i < 4; i++)
#pragma unroll
        for (int j = 0; j < 4; j++)
            p[(tc * 4 + i) * 64 + (td * 4 + j)] = acc[i][j];
}

// ---------------- softmax ----------------------------------------------------
__global__ __launch_bounds__(256) void softmax_k(
    const float* __restrict__ scp, float* __restrict__ s)
{
    __shared__ float red[8];
    const int b = blockIdx.x >> 6, d = blockIdx.x & 63;
    const int t = threadIdx.x;
    const float scale = 1.f / 24.f;

    float v[3];
#pragma unroll
    for (int u = 0; u < 3; u++) {
        int e = t + u * 256;
        if (e < 576) {
            int c = e / 9, k = e - c * 9;
            float sum = 0.f;
#pragma unroll
            for (int chn = 0; chn < 4; chn++)
                sum += scp[((size_t)((chn * 16 + b) * 9 + k)) * 4096 + c * 64 + d];
            v[u] = sum * scale;
        } else v[u] = -3.4e38f;
    }

    float m = fmaxf(fmaxf(v[0], v[1]), v[2]);
#pragma unroll
    for (int o = 16; o; o >>= 1) m = fmaxf(m, __shfl_xor_sync(0xffffffffu, m, o));
    if ((t & 31) == 0) red[t >> 5] = m;
    __syncthreads();
    m = fmaxf(fmaxf(fmaxf(red[0], red[1]), fmaxf(red[2], red[3])),
              fmaxf(fmaxf(red[4], red[5]), fmaxf(red[6], red[7])));
    __syncthreads();

    float e0 = __expf(v[0] - m), e1 = __expf(v[1] - m);
    float e2 = (t + 512) < 576 ? __expf(v[2] - m) : 0.f;
    float sum = e0 + e1 + e2;
#pragma unroll
    for (int o = 16; o; o >>= 1) sum += __shfl_xor_sync(0xffffffffu, sum, o);
    if ((t & 31) == 0) red[t >> 5] = sum;
    __syncthreads();
    sum = red[0] + red[1] + red[2] + red[3] + red[4] + red[5] + red[6] + red[7];

    float inv = 1.f / sum;
    float* p = s + (size_t)(b * C_ + d) * 576;
    p[t] = e0 * inv;
    p[t + 256] = e1 * inv;
    if (t + 512 < 576) p[t + 512] = e2 * inv;
}

// ---------------- launch -----------------------------------------------------
extern "C" void kernel_launch(void* const* d_in, const int* in_sizes, int n_in,
                              void* d_out, int out_size)
{
    const float* x1 = (const float*)d_in[0];
    const float* x2 = (const float*)d_in[1];
    const float* w1 = (const float*)d_in[2];
    const float* w2 = (const float*)d_in[3];
    const float* w3 = (const float*)d_in[4];
    float* out = (float*)d_out;

    float *kf, *qf, *sc, *scp;
    __half *Xh, *Xl, *Bh, *Bl;
    cudaGetSymbolAddress((void**)&kf, g_kf);
    cudaGetSymbolAddress((void**)&qf, g_qf);
    cudaGetSymbolAddress((void**)&sc, g_sc);
    cudaGetSymbolAddress((void**)&scp, g_scp);
    cudaGetSymbolAddress((void**)&Xh, g_Xh);
    cudaGetSymbolAddress((void**)&Xl, g_Xl);
    cudaGetSymbolAddress((void**)&Bh, g_Bh);
    cudaGetSymbolAddress((void**)&Bl, g_Bl);

    const int SMEM = 51840 + 2 * 64 * 144 * 2;    // 88704 (both configs)
    cudaFuncSetAttribute((const void*)conv_mma_k<128, false>,
                         cudaFuncAttributeMaxDynamicSharedMemorySize, SMEM);
    cudaFuncSetAttribute((const void*)conv_mma_k<64, true>,
                         cudaFuncAttributeMaxDynamicSharedMemorySize, SMEM);

    convert_x_k<<<dim3(96, 16, 2), 256>>>(x1, x2, Xh, Xl);
    convert_w_k<<<dim3(576, 1), 64>>>(w1, Bh, Bl, 0, 0, 0);
    convert_w_k<<<dim3(576, 1), 64>>>(w2, Bh, Bl, 576, 0, 0);
    convert_w_k<<<dim3(576, 1), 64>>>(w3, Bh, Bl, 1152, 0, 0);

    dim3 g(6, 12, 16);
    // fused kf (co 0-63, fp32) + vf (co 64-127 -> fp16 hi/lo pixel-major)
    conv_mma_k<128, false><<<g, 256, SMEM>>>(Xh, Xl, Bh, Bl, 0, 0, 1152, 0, 2, kf, Xh, Xl);
    // qf: per-tap double-buffered B
    conv_mma_k<64, true><<<g, 256, SMEM>>>(Xh, Xl, Bh, Bl, 16, 576, 0, 0, 0, qf, 0, 0);

    scores_k<<<dim3(9, 4, 16), 256>>>(kf, qf, scp);
    softmax_k<<<B_ * C_, 256>>>(scp, sc);
    convert_w_k<<<dim3(576, 16), 64>>>(sc, Bh, Bl, 1728, C_ * 576, 576);

    // dynamic conv on vf: per-batch weights, row stride 576
    conv_mma_k<64, true><<<g, 256, SMEM>>>(Xh, Xl, Bh, Bl, 32, 1728, 0, 576, 0, out, 0, 0);
}

// round 16
// speedup vs baseline: 1.1656x; 1.0104x over previous
#include <cuda_runtime.h>
#include <cuda_fp16.h>
#include <cstddef>

typedef unsigned int u32;
typedef unsigned long long ull;

#define B_   16
#define C_   64
#define HW_  96

// ---------------- scratch ----------------------------------------------------
__device__ float g_kf[(size_t)B_ * C_ * HW_ * HW_];
__device__ float g_qf[(size_t)B_ * C_ * HW_ * HW_];
__device__ float g_sc[(size_t)B_ * C_ * 576];
__device__ float g_scp[(size_t)4 * B_ * 9 * 64 * 64];
// pixel-major fp16 hi/lo: [img][y][x][ci]; img 0-15:x1, 16-31:x2, 32-47:vf
__device__ __half g_Xh[(size_t)48 * HW_ * HW_ * 64];
__device__ __half g_Xl[(size_t)48 * HW_ * HW_ * 64];
// weight rows [row][ci]: 0-575 w1, 576-1151 w2, 1152-1727 w3, 1728+ dyn (576/b)
__device__ __half g_Bh[(size_t)11008 * 64];
__device__ __half g_Bl[(size_t)11008 * 64];

// ---------------- helpers ------------------------------------------------
__device__ __forceinline__ u32 s2u(const void* p) {
    u32 a; asm("{ .reg .u64 t; cvta.to.shared.u64 t, %1; cvt.u32.u64 %0, t; }" : "=r"(a) : "l"(p));
    return a;
}
__device__ __forceinline__ void ldsm4(u32& r0, u32& r1, u32& r2, u32& r3, u32 addr) {
    asm volatile("ldmatrix.sync.aligned.m8n8.x4.shared.b16 {%0,%1,%2,%3}, [%4];"
        : "=r"(r0), "=r"(r1), "=r"(r2), "=r"(r3) : "r"(addr));
}
__device__ __forceinline__ void mma16816(float* d, const u32* a, const u32* b) {
    asm volatile("mma.sync.aligned.m16n8k16.row.col.f32.f16.f16.f32 "
        "{%0,%1,%2,%3}, {%4,%5,%6,%7}, {%8,%9}, {%0,%1,%2,%3};"
        : "+f"(d[0]), "+f"(d[1]), "+f"(d[2]), "+f"(d[3])
        : "r"(a[0]), "r"(a[1]), "r"(a[2]), "r"(a[3]), "r"(b[0]), "r"(b[1]));
}
// packed fp32x2 (FFMA2)
__device__ __forceinline__ ull pack2(float a, float b) {
    ull r; asm("mov.b64 %0, {%1, %2};" : "=l"(r) : "f"(a), "f"(b)); return r;
}
__device__ __forceinline__ void fma2(ull& d, ull a, ull b) {
    asm("fma.rn.f32x2 %0, %1, %2, %3;" : "=l"(d) : "l"(a), "l"(b), "l"(d));
}
__device__ __forceinline__ float2 unpack2(ull v) {
    float2 r; asm("mov.b64 {%0, %1}, %2;" : "=f"(r.x), "=f"(r.y) : "l"(v)); return r;
}
// cp.async (sm_80 baseline)
#define CPA16(s, g)     asm volatile("cp.async.cg.shared.global [%0], [%1], 16;" :: "r"(s), "l"(g))
#define CPA16Z(s, g, p) asm volatile("cp.async.cg.shared.global [%0], [%1], 16, %2;" :: "r"(s), "l"(g), "r"(p))
#define CPA_COMMIT()    asm volatile("cp.async.commit_group;")
#define CPA_WAIT0()     asm volatile("cp.async.wait_group 0;")

// smem layout (144B row pitch; bank stride 4 -> conflict-free LDSM)
#define AH_OFF 0
#define AL_OFF 25920
#define BB_OFF 51840
// B stage: hi rows then lo rows; NCO=64 double-buffered (2 stages), NCO=128 single.
// Both configs total 88704 bytes -> 2 blocks/SM.

// ---------------- mma conv ---------------------------------------------------
// mode 0: fp32 planar out. mode 2 (NCO=128): co<64 -> fp32 kf, co>=64 -> Vh/Vl.
template<int NCO, bool DB>
__global__ void __launch_bounds__(256) conv_mma_k(
    const __half* __restrict__ Xh, const __half* __restrict__ Xl,
    const __half* __restrict__ Bh, const __half* __restrict__ Bl,
    int aBase, int brow1, int brow2, int bRowStride, int mode,
    float* __restrict__ outF, __half* __restrict__ Vh, __half* __restrict__ Vl)
{
    constexpr int NF = NCO / 16;          // n-frags of 8 co per warp
    constexpr int NJ = NCO / 32;          // 16-co ldsm tiles per warp
    constexpr int BSTG = NCO * 144 * 2;   // one stage: hi + lo
    constexpr int BLO  = NCO * 144;       // lo offset within stage

    extern __shared__ __align__(16) char sm[];
    const u32 sb = s2u(sm);
    const int t = threadIdx.x, lane = t & 31, wid = t >> 5;
    const int m0 = (wid & 3) * 32, n0 = (wid >> 2) * (NCO / 2);
    const int b = blockIdx.z;
    const int x0 = blockIdx.x * 16, y0 = blockIdx.y * 8;
    const int br1 = brow1 + b * bRowStride;

    // ---- stage halo once via cp.async: 180 rows (10y x 18x) x 8 segs, hi+lo ----
    {
        const __half* XhB = Xh + (size_t)(aBase + b) * 9216 * 64;
        const __half* XlB = Xl + (size_t)(aBase + b) * 9216 * 64;
        for (int i = t; i < 1440; i += 256) {
            int row = i >> 3, seg = i & 7;
            int hy = row / 18, hx = row - hy * 18;
            int gy = y0 + hy - 1, gx = x0 + hx - 1;
            bool ok = ((unsigned)gy < 96u) && ((unsigned)gx < 96u);
            int cg = ok ? (gy * 96 + gx) : 0;
            size_t g = (size_t)cg * 64 + seg * 8;
            u32 p = ok ? 16u : 0u;
            CPA16Z(sb + AH_OFF + row * 144 + seg * 16, XhB + g, p);
            CPA16Z(sb + AL_OFF + row * 144 + seg * 16, XlB + g, p);
        }
    }

    // B staging: issue cp.asyncs for one tap into stage sidx (+commit)
    auto stageB = [&](int sidx, int tap) {
        u32 bb = sb + BB_OFF + sidx * BSTG;
        for (int i = t; i < NCO * 8; i += 256) {
            int co = i >> 3, seg = i & 7;
            int src = (NCO == 128 && co >= 64) ? (brow2 + tap * 64 + co - 64)
                                               : (br1 + tap * 64 + co);
            size_t g = (size_t)src * 64 + seg * 8;
            CPA16(bb + co * 144 + seg * 16, Bh + g);
            CPA16(bb + BLO + co * 144 + seg * 16, Bl + g);
        }
        CPA_COMMIT();
    };

    // lane geometry
    const int aRowL = (lane & 7) + 8 * ((lane >> 3) & 1);
    const int aKb   = 16 * (lane >> 4);
    const int bCoL  = (lane & 7) + 8 * (lane >> 4);
    const int bKb   = 16 * ((lane >> 3) & 1);

    float acc[2][NF][4];
#pragma unroll
    for (int i = 0; i < 2; i++)
#pragma unroll
        for (int j = 0; j < NF; j++)
#pragma unroll
            for (int k = 0; k < 4; k++) acc[i][j][k] = 0.f;

    if (DB) {
        stageB(0, 0);          // halo group + stage0 group in flight
        CPA_WAIT0();
    } else {
        CPA_COMMIT();          // halo group
        CPA_WAIT0();
    }
    __syncthreads();

#pragma unroll 1
    for (int tap = 0; tap < 9; tap++) {
        int bStage;
        if (DB) {
            bStage = tap & 1;
            if (tap < 8) stageB(bStage ^ 1, tap + 1);   // copies fly during compute
        } else {
            if (tap) __syncthreads();   // prior tap ldsm done before overwrite
            stageB(0, tap);
            CPA_WAIT0();
            __syncthreads();
            bStage = 0;
        }

        const int kh = tap / 3, kw = tap - kh * 3;
        const u32 bbase = sb + BB_OFF + bStage * BSTG;
        u32 aAddr[2], bAddr[NJ];
#pragma unroll
        for (int f = 0; f < 2; f++) {
            int px = m0 + f * 16 + aRowL;
            int r = ((px >> 4) + kh) * 18 + (px & 15) + kw;
            aAddr[f] = sb + AH_OFF + r * 144 + aKb;
        }
#pragma unroll
        for (int j = 0; j < NJ; j++)
            bAddr[j] = bbase + (n0 + j * 16 + bCoL) * 144 + bKb;

#pragma unroll
        for (int ks = 0; ks < 4; ks++) {
            u32 Ah[2][4], Al[2][4], Bhf[NJ][4], Blf[NJ][4];
#pragma unroll
            for (int f = 0; f < 2; f++) {
                u32 a = aAddr[f] + ks * 32;
                ldsm4(Ah[f][0], Ah[f][1], Ah[f][2], Ah[f][3], a);
                ldsm4(Al[f][0], Al[f][1], Al[f][2], Al[f][3], a + (AL_OFF - AH_OFF));
            }
#pragma unroll
            for (int j = 0; j < NJ; j++) {
                u32 a = bAddr[j] + ks * 32;
                ldsm4(Bhf[j][0], Bhf[j][1], Bhf[j][2], Bhf[j][3], a);
                ldsm4(Blf[j][0], Blf[j][1], Blf[j][2], Blf[j][3], a + BLO);
            }
            // product-major order: long dependency distance on each acc
#pragma unroll
            for (int mf = 0; mf < 2; mf++)
#pragma unroll
                for (int nf = 0; nf < NF; nf++)
                    mma16816(acc[mf][nf], Ah[mf], &Bhf[nf >> 1][(nf & 1) * 2]);
#pragma unroll
            for (int mf = 0; mf < 2; mf++)
#pragma unroll
                for (int nf = 0; nf < NF; nf++)
                    mma16816(acc[mf][nf], Ah[mf], &Blf[nf >> 1][(nf & 1) * 2]);
#pragma unroll
            for (int mf = 0; mf < 2; mf++)
#pragma unroll
                for (int nf = 0; nf < NF; nf++)
                    mma16816(acc[mf][nf], Al[mf], &Bhf[nf >> 1][(nf & 1) * 2]);
        }
        if (DB) {
            if (tap < 8) CPA_WAIT0();   // next stage's copies landed
            __syncthreads();            // reads done + copies visible to all
        }
    }

    // ---- epilogue ----
    const int g = lane >> 2, tt = lane & 3;
    const bool toHalf = (mode == 2) && (n0 >= 64);
    if (!toHalf) {
        float* ob = outF + (size_t)b * C_ * 9216;
#pragma unroll
        for (int mf = 0; mf < 2; mf++)
#pragma unroll
            for (int nf = 0; nf < NF; nf++) {
                int co = n0 + nf * 8 + 2 * tt;
#pragma unroll
                for (int h = 0; h < 2; h++) {
                    int px = m0 + mf * 16 + g + h * 8;
                    int y = y0 + (px >> 4), x = x0 + (px & 15);
                    ob[(size_t)co * 9216 + y * 96 + x]       = acc[mf][nf][2 * h];
                    ob[(size_t)(co + 1) * 9216 + y * 96 + x] = acc[mf][nf][2 * h + 1];
                }
            }
    } else {
#pragma unroll
        for (int mf = 0; mf < 2; mf++)
#pragma unroll
            for (int nf = 0; nf < NF; nf++) {
                int col = nf * 8 + 2 * tt;   // local co within vf (warp covers 64)
#pragma unroll
                for (int h = 0; h < 2; h++) {
                    int px = m0 + mf * 16 + g + h * 8;
                    int y = y0 + (px >> 4), x = x0 + (px & 15);
                    size_t ad = ((size_t)(32 + b) * 9216 + (size_t)y * 96 + x) * 64 + col;
                    float v0 = acc[mf][nf][2 * h], v1 = acc[mf][nf][2 * h + 1];
                    __half h0 = __float2half(v0), h1 = __float2half(v1);
                    __half l0 = __float2half(v0 - __half2float(h0));
                    __half l1 = __float2half(v1 - __half2float(h1));
                    *(__half2*)(Vh + ad) = __halves2half2(h0, h1);
                    *(__half2*)(Vl + ad) = __halves2half2(l0, l1);
                }
            }
    }
}

// ---------------- input transpose + fp16 hi/lo split -------------------------
__global__ __launch_bounds__(256) void convert_x_k(
    const float* __restrict__ x1, const float* __restrict__ x2,
    __half* __restrict__ Xh, __half* __restrict__ Xl)
{
    __shared__ float smt[96 * 65];
    const int y = blockIdx.x, b = blockIdx.y, src = blockIdx.z;
    const int t = threadIdx.x;
    const float* xp = (src ? x2 : x1) + (size_t)b * C_ * 9216 + (size_t)y * 96;
    for (int idx = t; idx < 64 * 96; idx += 256) {
        int ci = idx / 96, x = idx - ci * 96;
        smt[x * 65 + ci] = xp[(size_t)ci * 9216 + x];
    }
    __syncthreads();
    size_t base = ((size_t)((src * 16 + b) * 96 + y)) * 96 * 64;
    for (int idx = t; idx < 96 * 64; idx += 256) {
        int x = idx >> 6, ci = idx & 63;
        float v = smt[x * 65 + ci];
        __half h = __float2half(v);
        Xh[base + idx] = h;
        Xl[base + idx] = __float2half(v - __half2float(h));
    }
}

// ---------------- weight gather + fp16 hi/lo split ---------------------------
__global__ __launch_bounds__(64) void convert_w_k(
    const float* __restrict__ w, __half* __restrict__ Bh, __half* __restrict__ Bl,
    int rowBase, int sStride, int rowBS)
{
    const int tap = blockIdx.x >> 6, co = blockIdx.x & 63, b = blockIdx.y, ci = threadIdx.x;
    float v = w[(size_t)b * sStride + co * 576 + ci * 9 + tap];
    size_t row = (size_t)(rowBase + b * rowBS + tap * 64 + co);
    __half h = __float2half(v);
    Bh[row * 64 + ci] = h;
    Bl[row * 64 + ci] = __float2half(v - __half2float(h));
}

// ---------------- scores partials: float4 LDS + FFMA2 ------------------------
__global__ __launch_bounds__(256) void scores_k(
    const float* __restrict__ kf, const float* __restrict__ qf, float* __restrict__ scp)
{
    __shared__ float ks[32][68];   // [wp][c], pitch 68 keeps float4 rows 16B-aligned
    __shared__ float qs[32][68];
    const int k = blockIdx.x, ch = blockIdx.y, b = blockIdx.z;
    const int kh = k / 3, kw = k - kh * 3;
    const int t = threadIdx.x;
    const int tc = t >> 4, td = t & 15;
    const float* kb = kf + (size_t)b * C_ * 9216;
    const float* qb = qf + (size_t)b * C_ * 9216;

    ull acc2[2][4] = {};   // acc2[i2][j] = (acc[2*i2][j], acc[2*i2+1][j])

#pragma unroll 1
    for (int hp = ch * 8; hp < ch * 8 + 8; hp++) {
        __syncthreads();
        const int y = hp * 3 + kh;
        for (int idx = t; idx < 2048; idx += 256) {
            int c = idx >> 5, wp = idx & 31;
            size_t off = ((size_t)c * 96 + y) * 96 + wp * 3 + kw;
            ks[wp][c] = kb[off];
            qs[wp][c] = qb[off];
        }
        __syncthreads();
#pragma unroll 4
        for (int l = 0; l < 32; l++) {
            float4 kv = *(const float4*)&ks[l][tc * 4];   // broadcast within warp
            float4 qv = *(const float4*)&qs[l][td * 4];
            ull k0 = pack2(kv.x, kv.y), k1 = pack2(kv.z, kv.w);
            ull q0 = pack2(qv.x, qv.x), q1 = pack2(qv.y, qv.y);
            ull q2 = pack2(qv.z, qv.z), q3 = pack2(qv.w, qv.w);
            fma2(acc2[0][0], k0, q0); fma2(acc2[1][0], k1, q0);
            fma2(acc2[0][1], k0, q1); fma2(acc2[1][1], k1, q1);
            fma2(acc2[0][2], k0, q2); fma2(acc2[1][2], k1, q2);
            fma2(acc2[0][3], k0, q3); fma2(acc2[1][3], k1, q3);
        }
    }
    float* p = scp + ((size_t)((ch * 16 + b) * 9 + k)) * 4096;
#pragma unroll
    for (int i2 = 0; i2 < 2; i2++)
#pragma unroll
        for (int j = 0; j < 4; j++) {
            float2 v = unpack2(acc2[i2][j]);
            p[(tc * 4 + 2 * i2) * 64 + (td * 4 + j)]     = v.x;
            p[(tc * 4 + 2 * i2 + 1) * 64 + (td * 4 + j)] = v.y;
        }
}

// ---------------- softmax ----------------------------------------------------
__global__ __launch_bounds__(256) void softmax_k(
    const float* __restrict__ scp, float* __restrict__ s)
{
    __shared__ float red[8];
    const int b = blockIdx.x >> 6, d = blockIdx.x & 63;
    const int t = threadIdx.x;
    const float scale = 1.f / 24.f;

    float v[3];
#pragma unroll
    for (int u = 0; u < 3; u++) {
        int e = t + u * 256;
        if (e < 576) {
            int c = e / 9, k = e - c * 9;
            float sum = 0.f;
#pragma unroll
            for (int chn = 0; chn < 4; chn++)
                sum += scp[((size_t)((chn * 16 + b) * 9 + k)) * 4096 + c * 64 + d];
            v[u] = sum * scale;
        } else v[u] = -3.4e38f;
    }

    float m = fmaxf(fmaxf(v[0], v[1]), v[2]);
#pragma unroll
    for (int o = 16; o; o >>= 1) m = fmaxf(m, __shfl_xor_sync(0xffffffffu, m, o));
    if ((t & 31) == 0) red[t >> 5] = m;
    __syncthreads();
    m = fmaxf(fmaxf(fmaxf(red[0], red[1]), fmaxf(red[2], red[3])),
              fmaxf(fmaxf(red[4], red[5]), fmaxf(red[6], red[7])));
    __syncthreads();

    float e0 = __expf(v[0] - m), e1 = __expf(v[1] - m);
    float e2 = (t + 512) < 576 ? __expf(v[2] - m) : 0.f;
    float sum = e0 + e1 + e2;
#pragma unroll
    for (int o = 16; o; o >>= 1) sum += __shfl_xor_sync(0xffffffffu, sum, o);
    if ((t & 31) == 0) red[t >> 5] = sum;
    __syncthreads();
    sum = red[0] + red[1] + red[2] + red[3] + red[4] + red[5] + red[6] + red[7];

    float inv = 1.f / sum;
    float* p = s + (size_t)(b * C_ + d) * 576;
    p[t] = e0 * inv;
    p[t + 256] = e1 * inv;
    if (t + 512 < 576) p[t + 512] = e2 * inv;
}

// ---------------- launch -----------------------------------------------------
extern "C" void kernel_launch(void* const* d_in, const int* in_sizes, int n_in,
                              void* d_out, int out_size)
{
    const float* x1 = (const float*)d_in[0];
    const float* x2 = (const float*)d_in[1];
    const float* w1 = (const float*)d_in[2];
    const float* w2 = (const float*)d_in[3];
    const float* w3 = (const float*)d_in[4];
    float* out = (float*)d_out;

    float *kf, *qf, *sc, *scp;
    __half *Xh, *Xl, *Bh, *Bl;
    cudaGetSymbolAddress((void**)&kf, g_kf);
    cudaGetSymbolAddress((void**)&qf, g_qf);
    cudaGetSymbolAddress((void**)&sc, g_sc);
    cudaGetSymbolAddress((void**)&scp, g_scp);
    cudaGetSymbolAddress((void**)&Xh, g_Xh);
    cudaGetSymbolAddress((void**)&Xl, g_Xl);
    cudaGetSymbolAddress((void**)&Bh, g_Bh);
    cudaGetSymbolAddress((void**)&Bl, g_Bl);

    const int SMEM = 51840 + 2 * 64 * 144 * 2;    // 88704 (both configs)
    cudaFuncSetAttribute((const void*)conv_mma_k<128, false>,
                         cudaFuncAttributeMaxDynamicSharedMemorySize, SMEM);
    cudaFuncSetAttribute((const void*)conv_mma_k<64, true>,
                         cudaFuncAttributeMaxDynamicSharedMemorySize, SMEM);

    convert_x_k<<<dim3(96, 16, 2), 256>>>(x1, x2, Xh, Xl);
    convert_w_k<<<dim3(576, 1), 64>>>(w1, Bh, Bl, 0, 0, 0);
    convert_w_k<<<dim3(576, 1), 64>>>(w2, Bh, Bl, 576, 0, 0);
    convert_w_k<<<dim3(576, 1), 64>>>(w3, Bh, Bl, 1152, 0, 0);

    dim3 g(6, 12, 16);
    // fused kf (co 0-63, fp32) + vf (co 64-127 -> fp16 hi/lo pixel-major)
    conv_mma_k<128, false><<<g, 256, SMEM>>>(Xh, Xl, Bh, Bl, 0, 0, 1152, 0, 2, kf, Xh, Xl);
    // qf: per-tap double-buffered B via cp.async
    conv_mma_k<64, true><<<g, 256, SMEM>>>(Xh, Xl, Bh, Bl, 16, 576, 0, 0, 0, qf, 0, 0);

    scores_k<<<dim3(9, 4, 16), 256>>>(kf, qf, scp);
    softmax_k<<<B_ * C_, 256>>>(scp, sc);
    convert_w_k<<<dim3(576, 16), 64>>>(sc, Bh, Bl, 1728, C_ * 576, 576);

    // dynamic conv on vf: per-batch weights, row stride 576
    conv_mma_k<64, true><<<g, 256, SMEM>>>(Xh, Xl, Bh, Bl, 32, 1728, 0, 576, 0, out, 0, 0);
}